// round 1
// baseline (speedup 1.0000x reference)
#include <cuda_runtime.h>
#include <math.h>

#define IMG 224
#define NB 128
#define NPTS 16384
#define PLANE (IMG*IMG)          // 50176
#define PLANE4 (PLANE/4)         // 12544

// Scratch: one accumulation plane per batch (25.7 MB), plus per-batch params.
__device__ float g_scratch[NB * PLANE];
__device__ float g_rot[NB][9];
__device__ float g_zmm[NB][2];   // zmin, zmax

// ---------------------------------------------------------------------------
// Kernel 1: per-batch rotation matrix + z min/max reduction. One block / batch.
// ---------------------------------------------------------------------------
__global__ void __launch_bounds__(256) k_minmax(const float* __restrict__ pts,
                                                const float* __restrict__ az,
                                                const float* __restrict__ el) {
    int b = blockIdx.x;
    float a = az[b], e = el[b];
    float ca = cosf(a), sa = sinf(a);
    float ce = cosf(e), se = sinf(e);
    // R = R_el @ R_az
    float r20 = -ce * sa, r21 = se, r22 = ce * ca;

    const float* p = pts + (size_t)b * NPTS * 3;
    float zmin = 1e30f, zmax = -1e30f;
    for (int i = threadIdx.x; i < NPTS; i += blockDim.x) {
        float x = p[3*i + 0];
        float y = p[3*i + 1];
        float z = p[3*i + 2];
        float zr = r20 * x + r21 * y + r22 * z;
        zmin = fminf(zmin, zr);
        zmax = fmaxf(zmax, zr);
    }
    // warp reduce
    #pragma unroll
    for (int o = 16; o > 0; o >>= 1) {
        zmin = fminf(zmin, __shfl_xor_sync(0xffffffffu, zmin, o));
        zmax = fmaxf(zmax, __shfl_xor_sync(0xffffffffu, zmax, o));
    }
    __shared__ float smin[8], smax[8];
    int w = threadIdx.x >> 5, l = threadIdx.x & 31;
    if (l == 0) { smin[w] = zmin; smax[w] = zmax; }
    __syncthreads();
    if (w == 0) {
        zmin = (l < 8) ? smin[l] : 1e30f;
        zmax = (l < 8) ? smax[l] : -1e30f;
        #pragma unroll
        for (int o = 4; o > 0; o >>= 1) {
            zmin = fminf(zmin, __shfl_xor_sync(0xffffffffu, zmin, o));
            zmax = fmaxf(zmax, __shfl_xor_sync(0xffffffffu, zmax, o));
        }
        if (l == 0) {
            g_zmm[b][0] = zmin;
            g_zmm[b][1] = zmax;
            g_rot[b][0] = ca;      g_rot[b][1] = 0.f;  g_rot[b][2] = sa;
            g_rot[b][3] = se * sa; g_rot[b][4] = ce;   g_rot[b][5] = -se * ca;
            g_rot[b][6] = r20;     g_rot[b][7] = r21;  g_rot[b][8] = r22;
        }
    }
}

// ---------------------------------------------------------------------------
// Kernel 2: zero the scratch planes (vectorized).
// ---------------------------------------------------------------------------
__global__ void __launch_bounds__(256) k_zero() {
    float4* s = reinterpret_cast<float4*>(g_scratch);
    int total = NB * PLANE4;
    int stride = gridDim.x * blockDim.x;
    float4 z = make_float4(0.f, 0.f, 0.f, 0.f);
    for (int i = blockIdx.x * blockDim.x + threadIdx.x; i < total; i += stride)
        s[i] = z;
}

// ---------------------------------------------------------------------------
// Kernel 3: rotate + bilinear splat with atomics. grid = (blocks_per_b, NB)
// ---------------------------------------------------------------------------
__global__ void __launch_bounds__(256) k_splat(const float* __restrict__ pts) {
    int b = blockIdx.y;
    __shared__ float R[9];
    __shared__ float zmm[2];
    if (threadIdx.x < 9) R[threadIdx.x] = g_rot[b][threadIdx.x];
    if (threadIdx.x < 2) zmm[threadIdx.x] = g_zmm[b][threadIdx.x];
    __syncthreads();

    int i = blockIdx.x * blockDim.x + threadIdx.x;
    if (i >= NPTS) return;

    const float* p = pts + (size_t)b * NPTS * 3 + (size_t)3 * i;
    float x = p[0], y = p[1], z = p[2];

    float xr = R[0]*x + R[1]*y + R[2]*z;
    float yr = R[3]*x + R[4]*y + R[5]*z;
    float zr = R[6]*x + R[7]*y + R[8]*z;

    float zmin = zmm[0], zmax = zmm[1];
    float feat = 0.3f + 0.7f * (zr - zmin) / (zmax - zmin + 1e-6f);

    float px = (xr + 1.0f) * 0.5f * IMG - 0.5f;
    float py = (yr + 1.0f) * 0.5f * IMG - 0.5f;
    float px1 = floorf(px), py1 = floorf(py);
    // mask: px1>=0 && py1>=0 && px1+1 < IMG && py1+1 < IMG
    if (px1 < 0.f || py1 < 0.f || px1 > (float)(IMG - 2) || py1 > (float)(IMG - 2))
        return;  // reference zeroes these contributions

    float fx = px - px1, fy = py - py1;
    float w11 = (1.f - fx) * (1.f - fy) * feat;
    float w12 = (1.f - fx) * fy * feat;
    float w21 = fx * (1.f - fy) * feat;
    float w22 = fx * fy * feat;

    int xi = (int)px1, yi = (int)py1;
    float* img = g_scratch + (size_t)b * PLANE;
    int base = yi * IMG + xi;
    atomicAdd(&img[base],            w11);
    atomicAdd(&img[base + IMG],      w12);
    atomicAdd(&img[base + 1],        w21);
    atomicAdd(&img[base + IMG + 1],  w22);
}

// ---------------------------------------------------------------------------
// Kernel 4: broadcast plane -> 3 channels (float4 vectorized).
// ---------------------------------------------------------------------------
__global__ void __launch_bounds__(256) k_bcast(float4* __restrict__ out) {
    const float4* src = reinterpret_cast<const float4*>(g_scratch);
    int total = NB * PLANE4;
    int stride = gridDim.x * blockDim.x;
    for (int i = blockIdx.x * blockDim.x + threadIdx.x; i < total; i += stride) {
        float4 v = src[i];
        int b = i / PLANE4;
        int r = i - b * PLANE4;
        float4* o = out + (size_t)b * 3 * PLANE4 + r;
        o[0]          = v;
        o[PLANE4]     = v;
        o[2 * PLANE4] = v;
    }
}

extern "C" void kernel_launch(void* const* d_in, const int* in_sizes, int n_in,
                              void* d_out, int out_size) {
    const float* pts = (const float*)d_in[0];
    const float* az  = (const float*)d_in[1];
    const float* el  = (const float*)d_in[2];
    float* out = (float*)d_out;

    k_minmax<<<NB, 256>>>(pts, az, el);

    int zero_blocks = (NB * PLANE4 + 255) / 256;
    if (zero_blocks > 1184) zero_blocks = 1184;  // ~8 blocks/SM grid-stride
    k_zero<<<zero_blocks, 256>>>();

    dim3 sgrid((NPTS + 255) / 256, NB);
    k_splat<<<sgrid, 256>>>(pts);

    int bc_blocks = (NB * PLANE4 + 255) / 256;
    if (bc_blocks > 1184) bc_blocks = 1184;
    k_bcast<<<bc_blocks, 256>>>((float4*)out);
}

// round 2
// speedup vs baseline: 1.2618x; 1.2618x over previous
#include <cuda_runtime.h>
#include <math.h>

#define IMG 224
#define NB 128
#define NPTS 16384
#define PLANE (IMG*IMG)          // 50176
#define PLANE4 (PLANE/4)         // 12544

__device__ float g_rot[NB][9];
__device__ float g_zmm[NB][2];   // zmin, zmax

// ---------------------------------------------------------------------------
// Kernel 1: zero channel-0 planes of the output (splat target).
// ---------------------------------------------------------------------------
__global__ void __launch_bounds__(256) k_zero(float4* __restrict__ out4) {
    int total = NB * PLANE4;
    int stride = gridDim.x * blockDim.x;
    float4 z = make_float4(0.f, 0.f, 0.f, 0.f);
    for (int i = blockIdx.x * blockDim.x + threadIdx.x; i < total; i += stride) {
        int b = i / PLANE4;
        int r = i - b * PLANE4;
        out4[(size_t)b * 3 * PLANE4 + r] = z;
    }
}

// ---------------------------------------------------------------------------
// Kernel 2: per-batch rotation matrix + z min/max. One 1024-thread block/batch.
// Vectorized: each thread loads 4 points (3 x float4) per iteration.
// ---------------------------------------------------------------------------
__global__ void __launch_bounds__(1024) k_minmax(const float* __restrict__ pts,
                                                 const float* __restrict__ az,
                                                 const float* __restrict__ el) {
    int b = blockIdx.x;
    float a = az[b], e = el[b];
    float ca = cosf(a), sa = sinf(a);
    float ce = cosf(e), se = sinf(e);
    float r20 = -ce * sa, r21 = se, r22 = ce * ca;

    const float4* p4 = reinterpret_cast<const float4*>(pts + (size_t)b * NPTS * 3);
    float zmin = 1e30f, zmax = -1e30f;

    // 4096 groups of 4 points; 1024 threads -> 4 groups per thread
    #pragma unroll
    for (int j = 0; j < 4; j++) {
        int g = threadIdx.x + j * 1024;
        float4 f0 = p4[3*g + 0];   // x0 y0 z0 x1
        float4 f1 = p4[3*g + 1];   // y1 z1 x2 y2
        float4 f2 = p4[3*g + 2];   // z2 x3 y3 z3
        float z0 = r20*f0.x + r21*f0.y + r22*f0.z;
        float z1 = r20*f0.w + r21*f1.x + r22*f1.y;
        float z2 = r20*f1.z + r21*f1.w + r22*f2.x;
        float z3 = r20*f2.y + r21*f2.z + r22*f2.w;
        zmin = fminf(zmin, fminf(fminf(z0, z1), fminf(z2, z3)));
        zmax = fmaxf(zmax, fmaxf(fmaxf(z0, z1), fmaxf(z2, z3)));
    }

    #pragma unroll
    for (int o = 16; o > 0; o >>= 1) {
        zmin = fminf(zmin, __shfl_xor_sync(0xffffffffu, zmin, o));
        zmax = fmaxf(zmax, __shfl_xor_sync(0xffffffffu, zmax, o));
    }
    __shared__ float smin[32], smax[32];
    int w = threadIdx.x >> 5, l = threadIdx.x & 31;
    if (l == 0) { smin[w] = zmin; smax[w] = zmax; }
    __syncthreads();
    if (w == 0) {
        zmin = smin[l];
        zmax = smax[l];
        #pragma unroll
        for (int o = 16; o > 0; o >>= 1) {
            zmin = fminf(zmin, __shfl_xor_sync(0xffffffffu, zmin, o));
            zmax = fmaxf(zmax, __shfl_xor_sync(0xffffffffu, zmax, o));
        }
        if (l == 0) {
            g_zmm[b][0] = zmin;
            g_zmm[b][1] = zmax;
            g_rot[b][0] = ca;      g_rot[b][1] = 0.f;  g_rot[b][2] = sa;
            g_rot[b][3] = se * sa; g_rot[b][4] = ce;   g_rot[b][5] = -se * ca;
            g_rot[b][6] = r20;     g_rot[b][7] = r21;  g_rot[b][8] = r22;
        }
    }
}

// ---------------------------------------------------------------------------
// Kernel 3: rotate + bilinear splat with atomics, directly into out channel 0.
// grid = (16, NB), 256 threads, 4 points/thread via float4 loads.
// ---------------------------------------------------------------------------
__device__ __forceinline__ void splat_one(float* img, float xr, float yr, float zr,
                                          float zmin, float inv_range) {
    float feat = 0.3f + 0.7f * (zr - zmin) * inv_range;
    float px = fmaf(xr + 1.0f, 0.5f * IMG, -0.5f);
    float py = fmaf(yr + 1.0f, 0.5f * IMG, -0.5f);
    float px1 = floorf(px), py1 = floorf(py);
    if (px1 < 0.f || py1 < 0.f || px1 > (float)(IMG - 2) || py1 > (float)(IMG - 2))
        return;
    float fx = px - px1, fy = py - py1;
    float gx = 1.f - fx, gy = 1.f - fy;
    int base = (int)py1 * IMG + (int)px1;
    atomicAdd(&img[base],           gx * gy * feat);
    atomicAdd(&img[base + 1],       fx * gy * feat);
    atomicAdd(&img[base + IMG],     gx * fy * feat);
    atomicAdd(&img[base + IMG + 1], fx * fy * feat);
}

__global__ void __launch_bounds__(256) k_splat(const float* __restrict__ pts,
                                               float* __restrict__ out) {
    int b = blockIdx.y;
    __shared__ float R[9];
    __shared__ float zmm[2];
    if (threadIdx.x < 9) R[threadIdx.x] = g_rot[b][threadIdx.x];
    if (threadIdx.x < 2) zmm[threadIdx.x] = g_zmm[b][threadIdx.x];
    __syncthreads();

    float r00 = R[0], r01 = R[1], r02 = R[2];
    float r10 = R[3], r11 = R[4], r12 = R[5];
    float r20 = R[6], r21 = R[7], r22 = R[8];
    float zmin = zmm[0];
    float inv_range = 1.0f / (zmm[1] - zmm[0] + 1e-6f);

    int g = blockIdx.x * 256 + threadIdx.x;   // group of 4 points, 0..4095
    const float4* p4 = reinterpret_cast<const float4*>(pts + (size_t)b * NPTS * 3);
    float4 f0 = p4[3*g + 0];   // x0 y0 z0 x1
    float4 f1 = p4[3*g + 1];   // y1 z1 x2 y2
    float4 f2 = p4[3*g + 2];   // z2 x3 y3 z3

    float* img = out + (size_t)b * 3 * PLANE;  // channel 0 plane

    {   // point 0
        float x = f0.x, y = f0.y, z = f0.z;
        splat_one(img, r00*x + r01*y + r02*z, r10*x + r11*y + r12*z,
                  r20*x + r21*y + r22*z, zmin, inv_range);
    }
    {   // point 1
        float x = f0.w, y = f1.x, z = f1.y;
        splat_one(img, r00*x + r01*y + r02*z, r10*x + r11*y + r12*z,
                  r20*x + r21*y + r22*z, zmin, inv_range);
    }
    {   // point 2
        float x = f1.z, y = f1.w, z = f2.x;
        splat_one(img, r00*x + r01*y + r02*z, r10*x + r11*y + r12*z,
                  r20*x + r21*y + r22*z, zmin, inv_range);
    }
    {   // point 3
        float x = f2.y, y = f2.z, z = f2.w;
        splat_one(img, r00*x + r01*y + r02*z, r10*x + r11*y + r12*z,
                  r20*x + r21*y + r22*z, zmin, inv_range);
    }
}

// ---------------------------------------------------------------------------
// Kernel 4: broadcast channel 0 -> channels 1 and 2 (float4).
// ---------------------------------------------------------------------------
__global__ void __launch_bounds__(256) k_bcast(float4* __restrict__ out4) {
    int total = NB * PLANE4;
    int stride = gridDim.x * blockDim.x;
    for (int i = blockIdx.x * blockDim.x + threadIdx.x; i < total; i += stride) {
        int b = i / PLANE4;
        int r = i - b * PLANE4;
        size_t base = (size_t)b * 3 * PLANE4 + r;
        float4 v = out4[base];
        out4[base + PLANE4]     = v;
        out4[base + 2 * PLANE4] = v;
    }
}

extern "C" void kernel_launch(void* const* d_in, const int* in_sizes, int n_in,
                              void* d_out, int out_size) {
    const float* pts = (const float*)d_in[0];
    const float* az  = (const float*)d_in[1];
    const float* el  = (const float*)d_in[2];
    float* out = (float*)d_out;

    int gs_blocks = (NB * PLANE4 + 255) / 256;
    if (gs_blocks > 1184) gs_blocks = 1184;

    k_zero<<<gs_blocks, 256>>>((float4*)out);
    k_minmax<<<NB, 1024>>>(pts, az, el);

    dim3 sgrid(16, NB);
    k_splat<<<sgrid, 256>>>(pts, out);

    k_bcast<<<gs_blocks, 256>>>((float4*)out);
}

// round 3
// speedup vs baseline: 1.6179x; 1.2822x over previous
#include <cuda_runtime.h>
#include <math.h>

#define IMG 224
#define NB 128
#define NPTS 16384
#define PLANE (IMG*IMG)          // 50176
#define PLANE4 (PLANE/4)         // 12544

__device__ float g_rot[NB][9];
__device__ float g_zmm[NB][2];   // zmin, zmax

// 8-byte vector float add-reduction to global (sm_90+).
__device__ __forceinline__ void red2(float* p, float a, float b) {
    asm volatile("red.global.add.v2.f32 [%0], {%1, %2};"
                 :: "l"(p), "f"(a), "f"(b) : "memory");
}

// ---------------------------------------------------------------------------
// Kernel 1: zero channel-0 planes of the output. grid (49, NB), no div/loop.
// ---------------------------------------------------------------------------
__global__ void __launch_bounds__(256) k_zero(float4* __restrict__ out4) {
    int r = blockIdx.x * 256 + threadIdx.x;      // 0..12543
    int b = blockIdx.y;
    out4[(size_t)b * 3 * PLANE4 + r] = make_float4(0.f, 0.f, 0.f, 0.f);
}

// ---------------------------------------------------------------------------
// Kernel 2: per-batch rotation matrix + z min/max. One 1024-thread block/batch.
// ---------------------------------------------------------------------------
__global__ void __launch_bounds__(1024) k_minmax(const float* __restrict__ pts,
                                                 const float* __restrict__ az,
                                                 const float* __restrict__ el) {
    int b = blockIdx.x;
    float a = az[b], e = el[b];
    float ca = cosf(a), sa = sinf(a);
    float ce = cosf(e), se = sinf(e);
    float r20 = -ce * sa, r21 = se, r22 = ce * ca;

    const float4* p4 = reinterpret_cast<const float4*>(pts + (size_t)b * NPTS * 3);
    float zmin = 1e30f, zmax = -1e30f;

    #pragma unroll
    for (int j = 0; j < 4; j++) {
        int g = threadIdx.x + j * 1024;
        float4 f0 = p4[3*g + 0];
        float4 f1 = p4[3*g + 1];
        float4 f2 = p4[3*g + 2];
        float z0 = r20*f0.x + r21*f0.y + r22*f0.z;
        float z1 = r20*f0.w + r21*f1.x + r22*f1.y;
        float z2 = r20*f1.z + r21*f1.w + r22*f2.x;
        float z3 = r20*f2.y + r21*f2.z + r22*f2.w;
        zmin = fminf(zmin, fminf(fminf(z0, z1), fminf(z2, z3)));
        zmax = fmaxf(zmax, fmaxf(fmaxf(z0, z1), fmaxf(z2, z3)));
    }

    #pragma unroll
    for (int o = 16; o > 0; o >>= 1) {
        zmin = fminf(zmin, __shfl_xor_sync(0xffffffffu, zmin, o));
        zmax = fmaxf(zmax, __shfl_xor_sync(0xffffffffu, zmax, o));
    }
    __shared__ float smin[32], smax[32];
    int w = threadIdx.x >> 5, l = threadIdx.x & 31;
    if (l == 0) { smin[w] = zmin; smax[w] = zmax; }
    __syncthreads();
    if (w == 0) {
        zmin = smin[l];
        zmax = smax[l];
        #pragma unroll
        for (int o = 16; o > 0; o >>= 1) {
            zmin = fminf(zmin, __shfl_xor_sync(0xffffffffu, zmin, o));
            zmax = fmaxf(zmax, __shfl_xor_sync(0xffffffffu, zmax, o));
        }
        if (l == 0) {
            g_zmm[b][0] = zmin;
            g_zmm[b][1] = zmax;
            g_rot[b][0] = ca;      g_rot[b][1] = 0.f;  g_rot[b][2] = sa;
            g_rot[b][3] = se * sa; g_rot[b][4] = ce;   g_rot[b][5] = -se * ca;
            g_rot[b][6] = r20;     g_rot[b][7] = r21;  g_rot[b][8] = r22;
        }
    }
}

// ---------------------------------------------------------------------------
// Kernel 3: rotate + bilinear splat. v2 vector reductions for even columns.
// ---------------------------------------------------------------------------
__device__ __forceinline__ void splat_one(float* img, float xr, float yr, float zr,
                                          float zmin, float inv_range) {
    float feat = 0.3f + 0.7f * (zr - zmin) * inv_range;
    float px = fmaf(xr + 1.0f, 0.5f * IMG, -0.5f);
    float py = fmaf(yr + 1.0f, 0.5f * IMG, -0.5f);
    float px1 = floorf(px), py1 = floorf(py);
    if (px1 < 0.f || py1 < 0.f || px1 > (float)(IMG - 2) || py1 > (float)(IMG - 2))
        return;
    float fx = px - px1, fy = py - py1;
    float gx = 1.f - fx, gy = 1.f - fy;
    float wa = gx * gy * feat;   // (yi  , xi  )
    float wb = fx * gy * feat;   // (yi  , xi+1)
    float wc = gx * fy * feat;   // (yi+1, xi  )
    float wd = fx * fy * feat;   // (yi+1, xi+1)
    int xi = (int)px1, yi = (int)py1;
    int base = yi * IMG + xi;
    if ((xi & 1) == 0) {
        red2(&img[base],       wa, wb);
        red2(&img[base + IMG], wc, wd);
    } else {
        atomicAdd(&img[base],           wa);
        atomicAdd(&img[base + 1],       wb);
        atomicAdd(&img[base + IMG],     wc);
        atomicAdd(&img[base + IMG + 1], wd);
    }
}

__global__ void __launch_bounds__(256) k_splat(const float* __restrict__ pts,
                                               float* __restrict__ out) {
    int b = blockIdx.y;
    __shared__ float R[9];
    __shared__ float zmm[2];
    if (threadIdx.x < 9) R[threadIdx.x] = g_rot[b][threadIdx.x];
    if (threadIdx.x < 2) zmm[threadIdx.x] = g_zmm[b][threadIdx.x];
    __syncthreads();

    float r00 = R[0], r01 = R[1], r02 = R[2];
    float r10 = R[3], r11 = R[4], r12 = R[5];
    float r20 = R[6], r21 = R[7], r22 = R[8];
    float zmin = zmm[0];
    float inv_range = 1.0f / (zmm[1] - zmm[0] + 1e-6f);

    int g = blockIdx.x * 256 + threadIdx.x;   // group of 4 points
    const float4* p4 = reinterpret_cast<const float4*>(pts + (size_t)b * NPTS * 3);
    float4 f0 = p4[3*g + 0];
    float4 f1 = p4[3*g + 1];
    float4 f2 = p4[3*g + 2];

    float* img = out + (size_t)b * 3 * PLANE;  // channel 0 plane

    {
        float x = f0.x, y = f0.y, z = f0.z;
        splat_one(img, r00*x + r01*y + r02*z, r10*x + r11*y + r12*z,
                  r20*x + r21*y + r22*z, zmin, inv_range);
    }
    {
        float x = f0.w, y = f1.x, z = f1.y;
        splat_one(img, r00*x + r01*y + r02*z, r10*x + r11*y + r12*z,
                  r20*x + r21*y + r22*z, zmin, inv_range);
    }
    {
        float x = f1.z, y = f1.w, z = f2.x;
        splat_one(img, r00*x + r01*y + r02*z, r10*x + r11*y + r12*z,
                  r20*x + r21*y + r22*z, zmin, inv_range);
    }
    {
        float x = f2.y, y = f2.z, z = f2.w;
        splat_one(img, r00*x + r01*y + r02*z, r10*x + r11*y + r12*z,
                  r20*x + r21*y + r22*z, zmin, inv_range);
    }
}

// ---------------------------------------------------------------------------
// Kernel 4: broadcast ch0 -> ch1, ch2. grid (49, NB). Streaming stores.
// ---------------------------------------------------------------------------
__global__ void __launch_bounds__(256) k_bcast(float4* __restrict__ out4) {
    int r = blockIdx.x * 256 + threadIdx.x;
    int b = blockIdx.y;
    size_t base = (size_t)b * 3 * PLANE4 + r;
    float4 v = out4[base];
    __stcs(&out4[base + PLANE4], v);
    __stcs(&out4[base + 2 * PLANE4], v);
}

extern "C" void kernel_launch(void* const* d_in, const int* in_sizes, int n_in,
                              void* d_out, int out_size) {
    const float* pts = (const float*)d_in[0];
    const float* az  = (const float*)d_in[1];
    const float* el  = (const float*)d_in[2];
    float* out = (float*)d_out;

    dim3 pgrid(49, NB);                 // 49*256 == PLANE4
    k_zero<<<pgrid, 256>>>((float4*)out);
    k_minmax<<<NB, 1024>>>(pts, az, el);

    dim3 sgrid(16, NB);
    k_splat<<<sgrid, 256>>>(pts, out);

    k_bcast<<<pgrid, 256>>>((float4*)out);
}

// round 4
// speedup vs baseline: 1.7646x; 1.0907x over previous
#include <cuda_runtime.h>
#include <math.h>

#define IMG 224
#define NB 128
#define NPTS 16384
#define PLANE (IMG*IMG)          // 50176
#define PLANE4 (PLANE/4)         // 12544

__device__ float g_rot[NB][9];
__device__ float g_zmm[NB][2];   // zmin, inv_range

// 8B / 16B vector float add-reductions to global (sm_90+).
__device__ __forceinline__ void red2(float* p, float a, float b) {
    asm volatile("red.global.add.v2.f32 [%0], {%1, %2};"
                 :: "l"(p), "f"(a), "f"(b) : "memory");
}
__device__ __forceinline__ void red4(float* p, float a, float b, float c, float d) {
    asm volatile("red.global.add.v4.f32 [%0], {%1, %2, %3, %4};"
                 :: "l"(p), "f"(a), "f"(b), "f"(c), "f"(d) : "memory");
}

// ---------------------------------------------------------------------------
// Kernel 1 (fused): zero ch0 plane + rotation matrix + z min/max per batch.
// One 1024-thread block per batch. Zero stores overlap the reduction reads.
// ---------------------------------------------------------------------------
__global__ void __launch_bounds__(1024) k_prep(const float* __restrict__ pts,
                                               const float* __restrict__ az,
                                               const float* __restrict__ el,
                                               float4* __restrict__ out4) {
    int b = blockIdx.x;

    // ---- zero channel-0 plane of this batch (independent of reduction) ----
    {
        float4 z = make_float4(0.f, 0.f, 0.f, 0.f);
        float4* dst = out4 + (size_t)b * 3 * PLANE4;
        #pragma unroll
        for (int j = 0; j < 13; j++) {
            int r = threadIdx.x + j * 1024;
            if (r < PLANE4) dst[r] = z;
        }
    }

    float a = az[b], e = el[b];
    float ca = cosf(a), sa = sinf(a);
    float ce = cosf(e), se = sinf(e);
    float r20 = -ce * sa, r21 = se, r22 = ce * ca;

    const float4* p4 = reinterpret_cast<const float4*>(pts + (size_t)b * NPTS * 3);
    float zmin = 1e30f, zmax = -1e30f;

    #pragma unroll
    for (int j = 0; j < 4; j++) {
        int g = threadIdx.x + j * 1024;
        float4 f0 = p4[3*g + 0];
        float4 f1 = p4[3*g + 1];
        float4 f2 = p4[3*g + 2];
        float z0 = r20*f0.x + r21*f0.y + r22*f0.z;
        float z1 = r20*f0.w + r21*f1.x + r22*f1.y;
        float z2 = r20*f1.z + r21*f1.w + r22*f2.x;
        float z3 = r20*f2.y + r21*f2.z + r22*f2.w;
        zmin = fminf(zmin, fminf(fminf(z0, z1), fminf(z2, z3)));
        zmax = fmaxf(zmax, fmaxf(fmaxf(z0, z1), fmaxf(z2, z3)));
    }

    #pragma unroll
    for (int o = 16; o > 0; o >>= 1) {
        zmin = fminf(zmin, __shfl_xor_sync(0xffffffffu, zmin, o));
        zmax = fmaxf(zmax, __shfl_xor_sync(0xffffffffu, zmax, o));
    }
    __shared__ float smin[32], smax[32];
    int w = threadIdx.x >> 5, l = threadIdx.x & 31;
    if (l == 0) { smin[w] = zmin; smax[w] = zmax; }
    __syncthreads();
    if (w == 0) {
        zmin = smin[l];
        zmax = smax[l];
        #pragma unroll
        for (int o = 16; o > 0; o >>= 1) {
            zmin = fminf(zmin, __shfl_xor_sync(0xffffffffu, zmin, o));
            zmax = fmaxf(zmax, __shfl_xor_sync(0xffffffffu, zmax, o));
        }
        if (l == 0) {
            g_zmm[b][0] = zmin;
            g_zmm[b][1] = 1.0f / (zmax - zmin + 1e-6f);
            g_rot[b][0] = ca;      g_rot[b][1] = 0.f;  g_rot[b][2] = sa;
            g_rot[b][3] = se * sa; g_rot[b][4] = ce;   g_rot[b][5] = -se * ca;
            g_rot[b][6] = r20;     g_rot[b][7] = r21;  g_rot[b][8] = r22;
        }
    }
}

// ---------------------------------------------------------------------------
// Kernel 2: rotate + bilinear splat. v2/v4 vector reductions (2.5 ops/point).
// ---------------------------------------------------------------------------
__device__ __forceinline__ void splat_one(float* img, float xr, float yr, float zr,
                                          float zmin, float inv_range) {
    float feat = 0.3f + 0.7f * (zr - zmin) * inv_range;
    float px = fmaf(xr + 1.0f, 0.5f * IMG, -0.5f);
    float py = fmaf(yr + 1.0f, 0.5f * IMG, -0.5f);
    float px1 = floorf(px), py1 = floorf(py);
    if (px1 < 0.f || py1 < 0.f || px1 > (float)(IMG - 2) || py1 > (float)(IMG - 2))
        return;
    float fx = px - px1, fy = py - py1;
    float gx = 1.f - fx, gy = 1.f - fy;
    float wa = gx * gy * feat;   // (yi  , xi  )
    float wb = fx * gy * feat;   // (yi  , xi+1)
    float wc = gx * fy * feat;   // (yi+1, xi  )
    float wd = fx * fy * feat;   // (yi+1, xi+1)
    int xi = (int)px1, yi = (int)py1;
    int base = yi * IMG + xi;
    int m = xi & 3;
    if ((m & 1) == 0) {                 // xi%4 == 0 or 2: 8B-aligned pair
        red2(&img[base],       wa, wb);
        red2(&img[base + IMG], wc, wd);
    } else if (m == 1) {                // pair inside one 16B quad at base-1
        red4(&img[base - 1],       0.f, wa, wb, 0.f);
        red4(&img[base - 1 + IMG], 0.f, wc, wd, 0.f);
    } else {                            // m == 3: quad straddle, scalar
        atomicAdd(&img[base],           wa);
        atomicAdd(&img[base + 1],       wb);
        atomicAdd(&img[base + IMG],     wc);
        atomicAdd(&img[base + IMG + 1], wd);
    }
}

__global__ void __launch_bounds__(256) k_splat(const float* __restrict__ pts,
                                               float* __restrict__ out) {
    int b = blockIdx.y;
    __shared__ float R[9];
    __shared__ float zmm[2];
    if (threadIdx.x < 9) R[threadIdx.x] = g_rot[b][threadIdx.x];
    if (threadIdx.x < 2) zmm[threadIdx.x] = g_zmm[b][threadIdx.x];
    __syncthreads();

    float r00 = R[0], r01 = R[1], r02 = R[2];
    float r10 = R[3], r11 = R[4], r12 = R[5];
    float r20 = R[6], r21 = R[7], r22 = R[8];
    float zmin = zmm[0];
    float inv_range = zmm[1];

    int g = blockIdx.x * 256 + threadIdx.x;   // group of 4 points
    const float4* p4 = reinterpret_cast<const float4*>(pts + (size_t)b * NPTS * 3);
    float4 f0 = p4[3*g + 0];
    float4 f1 = p4[3*g + 1];
    float4 f2 = p4[3*g + 2];

    float* img = out + (size_t)b * 3 * PLANE;  // channel 0 plane

    {
        float x = f0.x, y = f0.y, z = f0.z;
        splat_one(img, r00*x + r01*y + r02*z, r10*x + r11*y + r12*z,
                  r20*x + r21*y + r22*z, zmin, inv_range);
    }
    {
        float x = f0.w, y = f1.x, z = f1.y;
        splat_one(img, r00*x + r01*y + r02*z, r10*x + r11*y + r12*z,
                  r20*x + r21*y + r22*z, zmin, inv_range);
    }
    {
        float x = f1.z, y = f1.w, z = f2.x;
        splat_one(img, r00*x + r01*y + r02*z, r10*x + r11*y + r12*z,
                  r20*x + r21*y + r22*z, zmin, inv_range);
    }
    {
        float x = f2.y, y = f2.z, z = f2.w;
        splat_one(img, r00*x + r01*y + r02*z, r10*x + r11*y + r12*z,
                  r20*x + r21*y + r22*z, zmin, inv_range);
    }
}

// ---------------------------------------------------------------------------
// Kernel 3: broadcast ch0 -> ch1, ch2. grid (25, NB), 2 float4 per thread.
// ---------------------------------------------------------------------------
__global__ void __launch_bounds__(256) k_bcast(float4* __restrict__ out4) {
    int r = blockIdx.x * 256 + threadIdx.x;      // 0..6399
    int b = blockIdx.y;
    size_t plane = (size_t)b * 3 * PLANE4;

    float4 v0 = out4[plane + r];
    int r1 = r + 6400;
    bool ok1 = (r1 < PLANE4);
    float4 v1;
    if (ok1) v1 = out4[plane + r1];

    __stcs(&out4[plane + PLANE4 + r], v0);
    __stcs(&out4[plane + 2 * PLANE4 + r], v0);
    if (ok1) {
        __stcs(&out4[plane + PLANE4 + r1], v1);
        __stcs(&out4[plane + 2 * PLANE4 + r1], v1);
    }
}

extern "C" void kernel_launch(void* const* d_in, const int* in_sizes, int n_in,
                              void* d_out, int out_size) {
    const float* pts = (const float*)d_in[0];
    const float* az  = (const float*)d_in[1];
    const float* el  = (const float*)d_in[2];
    float* out = (float*)d_out;

    k_prep<<<NB, 1024>>>(pts, az, el, (float4*)out);

    dim3 sgrid(16, NB);
    k_splat<<<sgrid, 256>>>(pts, out);

    dim3 bgrid(25, NB);
    k_bcast<<<bgrid, 256>>>((float4*)out);
}